// round 15
// baseline (speedup 1.0000x reference)
#include <cuda_runtime.h>
#include <cuda_bf16.h>
#include <cstdint>

// SpatialAttentionLayer_23381801959766
//
// Reference math: layer is algebraically the identity on X (softmax rows sum
// to 1 and are contracted out) -> 142.6 MB HBM streaming copy.
//
// R2-R14: ~6.0-6.1 TB/s plateau (36.7-39.0us kernel), invariant under vector
// width, MLP, all L2 policies, residency pinning, persistent grids.
// R10 lesson: the CTA scheduler's pipelining of independent front-batched
// load groups is the latency-hiding mechanism (persistent loops regressed).
// R15 probe: push that mechanism further — HALVE work per CTA (1 v8 load +
// 1 v8 store per thread, 32B/thread), doubling to 17408 independently
// schedulable CTAs. Pin split preserved at the 100MB boundary (12800 blocks).

static constexpr int THREADS = 256;
static constexpr size_t FLOATS_PER_BLOCK = (size_t)THREADS * 8;  // 8 KB
static constexpr unsigned PIN_BLOCKS = 12800;  // 100 MB boundary of out

__device__ __forceinline__ void ldg256_cs(const float* __restrict__ p, float* v) {
    asm volatile(
        "ld.global.cs.v8.f32 {%0,%1,%2,%3,%4,%5,%6,%7}, [%8];"
        : "=f"(v[0]), "=f"(v[1]), "=f"(v[2]), "=f"(v[3]),
          "=f"(v[4]), "=f"(v[5]), "=f"(v[6]), "=f"(v[7])
        : "l"(p));
}

__device__ __forceinline__ void stg256_el(float* __restrict__ p, const float* v) {
    asm volatile(
        "st.global.L2::evict_last.v8.f32 [%0], {%1,%2,%3,%4,%5,%6,%7,%8};"
        :: "l"(p),
           "f"(v[0]), "f"(v[1]), "f"(v[2]), "f"(v[3]),
           "f"(v[4]), "f"(v[5]), "f"(v[6]), "f"(v[7])
        : "memory");
}

__device__ __forceinline__ void stg256_cs(float* __restrict__ p, const float* v) {
    asm volatile(
        "st.global.cs.v8.f32 [%0], {%1,%2,%3,%4,%5,%6,%7,%8};"
        :: "l"(p),
           "f"(v[0]), "f"(v[1]), "f"(v[2]), "f"(v[3]),
           "f"(v[4]), "f"(v[5]), "f"(v[6]), "f"(v[7])
        : "memory");
}

__global__ __launch_bounds__(THREADS)
void stream_copy_kernel(const float* __restrict__ in, float* __restrict__ out) {
    size_t base = (size_t)blockIdx.x * FLOATS_PER_BLOCK + (size_t)threadIdx.x * 8;

    float v[8];
    ldg256_cs(in + base, v);           // one streaming v8 load

    if (blockIdx.x < PIN_BLOCKS) {
        stg256_el(out + base, v);      // write-residency region
    } else {
        stg256_cs(out + base, v);      // streaming write tail
    }
}

// Tail kernel for any remainder (unused at this exact shape).
__global__ void stream_copy_tail(const float* __restrict__ in,
                                 float* __restrict__ out,
                                 size_t start, size_t n) {
    size_t i = start + blockIdx.x * (size_t)blockDim.x + threadIdx.x;
    if (i < n) out[i] = __ldcs(in + i);
}

extern "C" void kernel_launch(void* const* d_in, const int* in_sizes, int n_in,
                              void* d_out, int out_size) {
    const float* X = (const float*)d_in[0];
    float* out = (float*)d_out;

    size_t n = (size_t)out_size;                 // 35,651,584 floats
    size_t full_blocks = n / FLOATS_PER_BLOCK;   // 17408 exact here

    if (full_blocks > 0) {
        stream_copy_kernel<<<(unsigned)full_blocks, THREADS>>>(X, out);
    }
    size_t done = full_blocks * FLOATS_PER_BLOCK;
    if (done < n) {
        size_t rem = n - done;
        unsigned tb = (unsigned)((rem + 255) / 256);
        stream_copy_tail<<<tb, 256>>>(X, out, done, n);
    }
}